// round 16
// baseline (speedup 1.0000x reference)
#include <cuda_runtime.h>
#include <cuda_fp16.h>
#include <math.h>
#include <stdint.h>

#define GN 3136          // H*W
#define CC 384
#define BB 8
#define NHEADS 8
#define HD 48
#define SZ (BB*CC*GN)    // 9,633,792

typedef __half h16;

// ---------------- scratch (static device globals; no runtime alloc) ----------------
__device__ __align__(16) float g_b1f[CC];
__device__ __align__(16) float g_dwf[CC*9];
__device__ __align__(16) float g_dbf[CC];
__device__ __align__(16) float g_kv[BB*NHEADS*HD*HD];
__device__ __align__(16) float g_ksum[BB*NHEADS*HD];

// fp16 activation buffers
__device__ __align__(16) h16 g_xh[SZ];
__device__ __align__(16) h16 g_cmid[SZ];         // conv mid (cw1 out, dwconv in)
__device__ __align__(16) h16 g_dwh[SZ];
__device__ __align__(16) h16 g_x1h[SZ];
__device__ __align__(16) h16 g_x2h[SZ];
__device__ __align__(16) h16 g_qkvh16[3*SZ];     // phi(q),phi(k),v
__device__ __align__(16) h16 g_aoh[SZ];
__device__ __align__(16) h16 g_lnh[SZ];
__device__ __align__(16) h16 g_hmh[4*SZ];
// fp16 weights
__device__ __align__(16) h16 g_w1fh[CC*CC];
__device__ __align__(16) h16 g_cw2h[CC*CC];
__device__ __align__(16) h16 g_qkvh[3*CC*CC];
__device__ __align__(16) h16 g_projh[CC*CC];
__device__ __align__(16) h16 g_w1th[CC*4*CC];
__device__ __align__(16) h16 g_w2th[CC*4*CC];

// ---------------- helpers ----------------
__device__ __forceinline__ void ldsm4(uint32_t* r, uint32_t a) {
    asm volatile("ldmatrix.sync.aligned.m8n8.x4.shared.b16 {%0,%1,%2,%3}, [%4];"
                 : "=r"(r[0]), "=r"(r[1]), "=r"(r[2]), "=r"(r[3]) : "r"(a));
}
__device__ __forceinline__ void ldsm4t(uint32_t* r, uint32_t a) {
    asm volatile("ldmatrix.sync.aligned.m8n8.x4.trans.shared.b16 {%0,%1,%2,%3}, [%4];"
                 : "=r"(r[0]), "=r"(r[1]), "=r"(r[2]), "=r"(r[3]) : "r"(a));
}
__device__ __forceinline__ void mma16816(float* c, const uint32_t* a, const uint32_t* b) {
    asm volatile("mma.sync.aligned.m16n8k16.row.col.f32.f16.f16.f32 "
                 "{%0,%1,%2,%3}, {%4,%5,%6,%7}, {%8,%9}, {%0,%1,%2,%3};"
                 : "+f"(c[0]), "+f"(c[1]), "+f"(c[2]), "+f"(c[3])
                 : "r"(a[0]), "r"(a[1]), "r"(a[2]), "r"(a[3]), "r"(b[0]), "r"(b[1]));
}
__device__ __forceinline__ void cpa16(uint32_t dst, const void* src) {
    asm volatile("cp.async.ca.shared.global [%0], [%1], 16;" :: "r"(dst), "l"(src));
}

// ---------------- BN1 folding (per-row reduction) ----------------
__global__ void fold_bn1_kernel(const float* __restrict__ cw1, const float* __restrict__ cb1,
                                const float* __restrict__ w, const float* __restrict__ bvec,
                                const float* __restrict__ m, const float* __restrict__ v) {
    int o = blockIdx.x;
    int tid = threadIdx.x;   // 128
    float part = 0.f;
    for (int i = tid; i < CC; i += 128) {
        float s = w[i] * rsqrtf(v[i] + 1e-5f);
        float t = bvec[i] - m[i] * s;
        float cv = cw1[o*CC + i];
        g_w1fh[o*CC + i] = __float2half_rn(cv * s);
        part += cv * t;
    }
    __shared__ float red[128];
    red[tid] = part; __syncthreads();
    for (int st = 64; st > 0; st >>= 1) { if (tid < st) red[tid] += red[tid+st]; __syncthreads(); }
    if (tid == 0) g_b1f[o] = cb1[o] + red[0];
}

// ---------------- fused elementwise prep ----------------
#define P0 384
#define P1 (P0 + BB*NHEADS*HD*HD + BB*NHEADS*HD)
#define P2 (P1 + CC*CC)
#define P3 (P2 + 3*CC*CC)
#define P4 (P3 + CC*CC)
#define P5 (P4 + CC*4*CC)
#define P6 (P5 + CC*4*CC)

__global__ void prep_all_kernel(const float* __restrict__ dw, const float* __restrict__ db,
                                const float* __restrict__ bw, const float* __restrict__ bb,
                                const float* __restrict__ bm, const float* __restrict__ bv,
                                const float* __restrict__ cw2, const float* __restrict__ qkv_w,
                                const float* __restrict__ proj_w,
                                const float* __restrict__ mlp_w1, const float* __restrict__ mlp_w2) {
    int i = blockIdx.x * 256 + threadIdx.x;
    if (i < P0) {
        int c = i;
        float s = bw[c] * rsqrtf(bv[c] + 1e-5f);
        float t = bb[c] - bm[c] * s;
        #pragma unroll
        for (int k = 0; k < 9; k++) g_dwf[c*9 + k] = dw[c*9 + k] * s;
        g_dbf[c] = db[c] * s + t;
    } else if (i < P1) {
        int j = i - P0;
        if (j < BB*NHEADS*HD*HD) g_kv[j] = 0.f;
        else g_ksum[j - BB*NHEADS*HD*HD] = 0.f;
    } else if (i < P2) {
        int j = i - P1; g_cw2h[j] = __float2half_rn(cw2[j]);
    } else if (i < P3) {
        int j = i - P2; g_qkvh[j] = __float2half_rn(qkv_w[j]);
    } else if (i < P4) {
        int j = i - P3; g_projh[j] = __float2half_rn(proj_w[j]);
    } else if (i < P5) {
        int j = i - P4;            // w1t: (1536 x 384) from (384 x 1536)
        int a = j / CC, bcol = j - a * CC;
        g_w1th[j] = __float2half_rn(mlp_w1[bcol * (4*CC) + a]);
    } else if (i < P6) {
        int j = i - P5;            // w2t: (384 x 1536) from (1536 x 384)
        int a = j / (4*CC), bcol = j - a * (4*CC);
        g_w2th[j] = __float2half_rn(mlp_w2[bcol * CC + a]);
    }
}

__global__ void tohalf_kernel(const float* __restrict__ src, h16* __restrict__ h, int n) {
    int i = blockIdx.x * 256 + threadIdx.x;
    if (i < n) h[i] = __float2half_rn(src[i]);
}

// ---------------- fp16 GEMM (tensor core, 3-stage cp.async pipeline) ----------------
// Y[b,o,n] = act(W[o,:]·X[b,:,n] + bias[o]) (+ res32 / + res16), fp16 in, fp32 accum.
// ACT: 0=none, 1=gelu, 2=phi on rows<2*CC.
// BM=128, BN=64, BK=32, 128 threads, 4 warps (2m x 2n), warp tile 64x32.
#define SM_B    8192
#define STAGE   12288

template<int ACT>
__global__ __launch_bounds__(128, 5)
void gemm_f16(const h16* __restrict__ Wh, const h16* __restrict__ Xh,
              const float* __restrict__ bias,
              const float* __restrict__ res, const h16* __restrict__ resH,
              float* __restrict__ YF, h16* __restrict__ YH,
              int Cout, int K) {
    const int b  = blockIdx.z;
    const int m0 = blockIdx.y * 128;
    const int n0 = blockIdx.x * 64;
    const h16* Xhb = Xh + (size_t)b * K * GN;
    const size_t obase = (size_t)b * Cout * GN;

    __shared__ __align__(16) unsigned char smraw[3 * STAGE];
    const uint32_t smbase = (uint32_t)__cvta_generic_to_shared(smraw);

    const int tid  = threadIdx.x;
    const int lane = tid & 31;
    const int wid  = tid >> 5;
    const int warp_m = wid & 1;
    const int warp_n = wid >> 1;
    const int m_base = warp_m * 64;
    const int n_base = warp_n * 32;

    const int r8   = (lane & 7) + ((lane >> 3) & 1) * 8;
    const int cadd = lane >> 4;

    float acc[4][4][4];
    #pragma unroll
    for (int i = 0; i < 4; i++)
        #pragma unroll
        for (int nt = 0; nt < 4; nt++)
            #pragma unroll
            for (int q = 0; q < 4; q++) acc[i][nt][q] = 0.f;

    const int ca  = tid & 3;
    const int cam = tid >> 2;
    const int cb  = tid & 7;
    const int cbm = tid >> 3;

    auto issue_tile = [&](int k0, int s) {
        uint32_t sb = smbase + s * STAGE;
        #pragma unroll
        for (int h = 0; h < 4; h++) {
            int m = cam + 32*h;
            uint32_t d = sb + m*64 + ((ca ^ ((m >> 1) & 3)) << 4);
            cpa16(d, Wh + (size_t)(m0 + m) * K + k0 + ca*8);
        }
        #pragma unroll
        for (int h = 0; h < 2; h++) {
            int k = cbm + 16*h;
            uint32_t d = sb + SM_B + k*128 + ((cb ^ (k & 7)) << 4);
            cpa16(d, Xhb + (size_t)(k0 + k) * GN + n0 + cb*8);
        }
        asm volatile("cp.async.commit_group;" ::: "memory");
    };

    const int NT = K >> 5;
    issue_tile(0, 0);
    issue_tile(32, 1);
    int sidx = 0;
    for (int t = 0; t < NT; t++) {
        if (t + 2 < NT) {
            asm volatile("cp.async.wait_group 1;" ::: "memory");
        } else {
            asm volatile("cp.async.wait_group 0;" ::: "memory");
        }
        __syncthreads();
        if (t + 2 < NT) {
            int s2 = sidx + 2; if (s2 >= 3) s2 -= 3;
            issue_tile((t + 2) * 32, s2);
        }
        uint32_t sb = smbase + sidx * STAGE;

        #pragma unroll
        for (int j = 0; j < 2; j++) {
            uint32_t ah[4][4], bh[4][2];
            #pragma unroll
            for (int i = 0; i < 4; i++) {
                int row = m_base + 16*i + r8;
                int ch = 2*j + cadd;
                ldsm4(ah[i], sb + row*64 + ((ch ^ ((row >> 1) & 3)) << 4));
            }
            #pragma unroll
            for (int u = 0; u < 2; u++) {
                int rowk = 16*j + r8;
                int nc = warp_n*4 + 2*u + cadd;
                uint32_t t4[4];
                ldsm4t(t4, sb + SM_B + rowk*128 + ((nc ^ (rowk & 7)) << 4));
                bh[2*u][0] = t4[0]; bh[2*u][1] = t4[1];
                bh[2*u+1][0] = t4[2]; bh[2*u+1][1] = t4[3];
            }
            #pragma unroll
            for (int i = 0; i < 4; i++)
                #pragma unroll
                for (int nt = 0; nt < 4; nt++)
                    mma16816(acc[i][nt], ah[i], bh[nt]);
        }
        if (++sidx == 3) sidx = 0;
    }

    // epilogue
    const int g = lane >> 2, tc = lane & 3;
    #pragma unroll
    for (int i = 0; i < 4; i++) {
        #pragma unroll
        for (int half = 0; half < 2; half++) {
            int row = m0 + m_base + 16*i + g + 8*half;
            float bv = bias ? bias[row] : 0.f;
            size_t rowoff = obase + (size_t)row * GN;
            bool do_phi = (ACT == 2) && (row < 2*CC);
            #pragma unroll
            for (int nt = 0; nt < 4; nt++) {
                int n = n0 + n_base + 8*nt + tc*2;
                float v0 = acc[i][nt][2*half + 0] + bv;
                float v1 = acc[i][nt][2*half + 1] + bv;
                if (ACT == 1) {
                    v0 = 0.5f * v0 * (1.f + erff(v0 * 0.70710678118654752f));
                    v1 = 0.5f * v1 * (1.f + erff(v1 * 0.70710678118654752f));
                }
                if (ACT == 2 && do_phi) {
                    v0 = expf(0.5f * (2.f*v0 - v0*v0));
                    v1 = expf(0.5f * (2.f*v1 - v1*v1));
                }
                if (res) {
                    float2 r = *reinterpret_cast<const float2*>(res + rowoff + n);
                    v0 += r.x; v1 += r.y;
                }
                if (resH) {
                    __half2 rh = *reinterpret_cast<const __half2*>(resH + rowoff + n);
                    v0 += __half2float(rh.x); v1 += __half2float(rh.y);
                }
                if (YF) *reinterpret_cast<float2*>(YF + rowoff + n) = make_float2(v0, v1);
                if (YH) {
                    __half2 ph; ph.x = __float2half_rn(v0); ph.y = __float2half_rn(v1);
                    *reinterpret_cast<__half2*>(YH + rowoff + n) = ph;
                }
            }
        }
    }
}

template<int ACT>
static void run_gemm(const h16* Wh, const h16* Xh, const float* bias,
                     const float* res, const h16* resH,
                     float* YF, h16* YH, int Cout, int K) {
    dim3 g(GN/64, Cout/128, BB), blk(128);
    gemm_f16<ACT><<<g, blk>>>(Wh, Xh, bias, res, resH, YF, YH, Cout, K);
}

// ---------------- depthwise 3x3 (BN2-folded), fp16 in/out ----------------
__global__ __launch_bounds__(256)
void dwconv_kernel(const h16* __restrict__ in, h16* __restrict__ oh) {
    int bc = blockIdx.x;          // b*CC + c
    int c  = bc % CC;
    __shared__ float tile[58*58];
    const h16* plane = in + (size_t)bc * GN;
    int tid = threadIdx.x;
    for (int idx = tid; idx < 58*58; idx += 256) {
        int ty = idx / 58, tx = idx - ty*58;
        int y = ty - 1, xq = tx - 1;
        float v = 0.f;
        if (y >= 0 && y < 56 && xq >= 0 && xq < 56) v = __half2float(plane[y*56 + xq]);
        tile[idx] = v;
    }
    __syncthreads();
    float w0=g_dwf[c*9+0], w1=g_dwf[c*9+1], w2=g_dwf[c*9+2];
    float w3=g_dwf[c*9+3], w4=g_dwf[c*9+4], w5=g_dwf[c*9+5];
    float w6=g_dwf[c*9+6], w7=g_dwf[c*9+7], w8=g_dwf[c*9+8];
    float bbv = g_dbf[c];
    h16* ohp = oh + (size_t)bc * GN;
    for (int p = tid; p < GN; p += 256) {
        int y = p / 56, xq = p - y*56;
        const float* t = &tile[y*58 + xq];
        float a = bbv + w0*t[0] + w1*t[1] + w2*t[2]
                      + w3*t[58] + w4*t[59] + w5*t[60]
                      + w6*t[116] + w7*t[117] + w8*t[118];
        ohp[p] = __float2half_rn(a);
    }
}

// ---------------- linear attention (qkv already phi-transformed for q,k) ----------------
// j-tile = 98: two sub-tiles per 196-position block.
__global__ __launch_bounds__(256)
void attn_kv_kernel(const h16* __restrict__ qkv) {
    int bh = blockIdx.x; int b = bh >> 3, hd = bh & 7;
    int n0 = blockIdx.y * 196;
    __shared__ float kp_s[98*48];
    __shared__ float vv_s[98*48];
    int tid = threadIdx.x;
    int dr[9], er[9];
    #pragma unroll
    for (int r = 0; r < 9; r++) { int de = tid + 256*r; dr[r] = de/48; er[r] = de - dr[r]*48; }
    float acc[9];
    #pragma unroll
    for (int r = 0; r < 9; r++) acc[r] = 0.f;
    float ks = 0.f;
    const h16* kbase = qkv + ((size_t)(b*1152 + CC   + hd*HD)) * GN + n0;
    const h16* vbase = qkv + ((size_t)(b*1152 + 2*CC + hd*HD)) * GN + n0;
    for (int j0 = 0; j0 < 196; j0 += 98) {
        for (int idx = tid; idx < 48*98; idx += 256) {
            int d = idx / 98, j = idx - d*98;
            kp_s[j*48 + d] = __half2float(kbase[(size_t)d*GN + j0 + j]);
            vv_s[j*48 + d] = __half2float(vbase[(size_t)d*GN + j0 + j]);
        }
        __syncthreads();
        #pragma unroll 2
        for (int j = 0; j < 98; j++) {
            #pragma unroll
            for (int r = 0; r < 9; r++)
                acc[r] = fmaf(kp_s[j*48 + dr[r]], vv_s[j*48 + er[r]], acc[r]);
        }
        if (tid < 48) {
            float s = 0.f;
            #pragma unroll 2
            for (int j = 0; j < 98; j++) s += kp_s[j*48 + tid];
            ks += s;
        }
        __syncthreads();
    }
    #pragma unroll
    for (int r = 0; r < 9; r++) atomicAdd(&g_kv[bh*2304 + tid + 256*r], acc[r]);
    if (tid < 48) atomicAdd(&g_ksum[bh*48 + tid], ks);
}

__global__ __launch_bounds__(256)
void attn_out_kernel(const h16* __restrict__ qkv, h16* __restrict__ oh) {
    int bh = blockIdx.x; int b = bh >> 3, hd = bh & 7;
    int n0 = blockIdx.y * 196;
    __shared__ float kv_s[2304];
    __shared__ float ks_s[48];
    __shared__ float qp_s[98*49];
    __shared__ float dinv[98];
    int tid = threadIdx.x;
    for (int i = tid; i < 2304; i += 256) kv_s[i] = g_kv[bh*2304 + i];
    if (tid < 48) ks_s[tid] = g_ksum[bh*48 + tid];
    __syncthreads();
    const h16* qbase = qkv + ((size_t)(b*1152 + hd*HD)) * GN + n0;
    size_t ob = ((size_t)(b*CC + hd*HD)) * GN + n0;
    for (int j0 = 0; j0 < 196; j0 += 98) {
        for (int idx = tid; idx < 48*98; idx += 256) {
            int d = idx / 98, j = idx - d*98;
            qp_s[j*49 + d] = __half2float(qbase[(size_t)d*GN + j0 + j]);
        }
        __syncthreads();
        if (tid < 98) {
            float s = 0.f;
            #pragma unroll
            for (int d = 0; d < 48; d++) s = fmaf(qp_s[tid*49 + d], ks_s[d], s);
            dinv[tid] = 1.f / (s + 1e-6f);
        }
        __syncthreads();
        for (int idx = tid; idx < 48*98; idx += 256) {
            int e = idx / 98, j = idx - e*98;
            float s = 0.f;
            #pragma unroll
            for (int d = 0; d < 48; d++) s = fmaf(qp_s[j*49 + d], kv_s[d*48 + e], s);
            oh[ob + (size_t)e*GN + j0 + j] = __float2half_rn(s * dinv[j]);
        }
        __syncthreads();
    }
}

// ---------------- LayerNorm over channels, fp16 in, writes fp16 ----------------
__global__ __launch_bounds__(256)
void ln_kernel(const h16* __restrict__ x2, const float* __restrict__ lw,
               const float* __restrict__ lb, h16* __restrict__ oh) {
    int b = blockIdx.y; int n0 = blockIdx.x * 16;
    __shared__ float s[CC*17];
    __shared__ float r1[256], r2[256];
    __shared__ float mu[16], ri[16];
    const h16* base = x2 + (size_t)b * CC * GN + n0;
    int tid = threadIdx.x;
    for (int idx = tid; idx < CC*16; idx += 256) {
        int c = idx >> 4, j = idx & 15;
        s[c*17 + j] = __half2float(base[(size_t)c * GN + j]);
    }
    __syncthreads();
    {
        int j = tid & 15, part = tid >> 4;
        float sm = 0.f, sq = 0.f;
        for (int c = part*24; c < part*24 + 24; c++) {
            float v = s[c*17 + j]; sm += v; sq = fmaf(v, v, sq);
        }
        r1[tid] = sm; r2[tid] = sq;
    }
    __syncthreads();
    if (tid < 16) {
        float a = 0.f, q = 0.f;
        #pragma unroll
        for (int p = 0; p < 16; p++) { a += r1[p*16 + tid]; q += r2[p*16 + tid]; }
        float mean = a * (1.f/384.f);
        float var = q * (1.f/384.f) - mean*mean;
        mu[tid] = mean; ri[tid] = rsqrtf(var + 1e-5f);
    }
    __syncthreads();
    size_t ob = (size_t)b * CC * GN + n0;
    for (int idx = tid; idx < CC*16; idx += 256) {
        int c = idx >> 4, j = idx & 15;
        float v = (s[c*17 + j] - mu[j]) * ri[j] * lw[c] + lb[c];
        oh[ob + (size_t)c * GN + j] = __float2half_rn(v);
    }
}

// ---------------- launch ----------------
extern "C" void kernel_launch(void* const* d_in, const int* in_sizes, int n_in,
                              void* d_out, int out_size) {
    const float* x      = (const float*)d_in[0];
    const float* bn1_w  = (const float*)d_in[1];
    const float* bn1_b  = (const float*)d_in[2];
    const float* bn1_m  = (const float*)d_in[3];
    const float* bn1_v  = (const float*)d_in[4];
    const float* cw1    = (const float*)d_in[5];
    const float* cb1    = (const float*)d_in[6];
    const float* dw     = (const float*)d_in[7];
    const float* db     = (const float*)d_in[8];
    const float* bn2_w  = (const float*)d_in[9];
    const float* bn2_b  = (const float*)d_in[10];
    const float* bn2_m  = (const float*)d_in[11];
    const float* bn2_v  = (const float*)d_in[12];
    const float* cw2    = (const float*)d_in[13];
    const float* cb2    = (const float*)d_in[14];
    const float* qkv_w  = (const float*)d_in[15];
    const float* proj_w = (const float*)d_in[16];
    const float* proj_b = (const float*)d_in[17];
    const float* ln_w   = (const float*)d_in[18];
    const float* ln_b   = (const float*)d_in[19];
    const float* mlp_w1 = (const float*)d_in[20];
    const float* mlp_b1 = (const float*)d_in[21];
    const float* mlp_w2 = (const float*)d_in[22];
    const float* mlp_b2 = (const float*)d_in[23];

    // symbol addresses
    float *b1f;
    h16 *xh,*cmid,*dwh,*x1h,*x2h,*qkvh16,*aoh,*lnh,*hmh;
    h16 *w1fh,*cw2h,*qkvh,*projh,*w1th,*w2th;
    cudaGetSymbolAddress((void**)&b1f,  g_b1f);
    cudaGetSymbolAddress((void**)&xh,  g_xh);
    cudaGetSymbolAddress((void**)&cmid, g_cmid);
    cudaGetSymbolAddress((void**)&dwh, g_dwh);
    cudaGetSymbolAddress((void**)&x1h, g_x1h);
    cudaGetSymbolAddress((void**)&x2h, g_x2h);
    cudaGetSymbolAddress((void**)&qkvh16, g_qkvh16);
    cudaGetSymbolAddress((void**)&aoh, g_aoh);
    cudaGetSymbolAddress((void**)&lnh, g_lnh);
    cudaGetSymbolAddress((void**)&hmh, g_hmh);
    cudaGetSymbolAddress((void**)&w1fh, g_w1fh);
    cudaGetSymbolAddress((void**)&cw2h, g_cw2h);
    cudaGetSymbolAddress((void**)&qkvh, g_qkvh);
    cudaGetSymbolAddress((void**)&projh, g_projh);
    cudaGetSymbolAddress((void**)&w1th, g_w1th);
    cudaGetSymbolAddress((void**)&w2th, g_w2th);

    // weight prep (3 launches)
    fold_bn1_kernel<<<CC, 128>>>(cw1, cb1, bn1_w, bn1_b, bn1_m, bn1_v);
    prep_all_kernel<<<(P6 + 255)/256, 256>>>(dw, db, bn2_w, bn2_b, bn2_m, bn2_v,
                                             cw2, qkv_w, proj_w, mlp_w1, mlp_w2);
    tohalf_kernel<<<(SZ + 255)/256, 256>>>(x, xh, SZ);

    // conv path
    run_gemm<0>(w1fh, xh, b1f, nullptr, nullptr, nullptr, cmid, CC, CC);
    dwconv_kernel<<<BB*CC, 256>>>(cmid, dwh);
    run_gemm<0>(cw2h, dwh, cb2, nullptr, xh, nullptr, x1h, CC, CC);   // x1 = 1x1 + x(h) -> fp16

    // linear attention (phi fused into qkv epilogue)
    run_gemm<2>(qkvh, x1h, nullptr, nullptr, nullptr, nullptr, qkvh16, 3*CC, CC);
    attn_kv_kernel<<<dim3(BB*NHEADS, 16), 256>>>(qkvh16);
    attn_out_kernel<<<dim3(BB*NHEADS, 16), 256>>>(qkvh16, aoh);
    run_gemm<0>(projh, aoh, proj_b, nullptr, x1h, nullptr, x2h, CC, CC);  // x2 = proj + x1 -> fp16

    // LN + MLP
    ln_kernel<<<dim3(GN/16, BB), 256>>>(x2h, ln_w, ln_b, lnh);
    run_gemm<1>(w1th, lnh, mlp_b1, nullptr, nullptr, nullptr, hmh, 4*CC, CC);        // gelu(fc1)
    run_gemm<0>(w2th, hmh, mlp_b2, nullptr, x2h, (float*)d_out, nullptr, CC, 4*CC);  // out = x2 + fc2
}

// round 17
// speedup vs baseline: 1.1845x; 1.1845x over previous
#include <cuda_runtime.h>
#include <cuda_fp16.h>
#include <math.h>
#include <stdint.h>

#define GN 3136          // H*W
#define CC 384
#define BB 8
#define NHEADS 8
#define HD 48
#define SZ (BB*CC*GN)    // 9,633,792

typedef __half h16;

// ---------------- scratch (static device globals; no runtime alloc) ----------------
__device__ __align__(16) float g_b1f[CC];
__device__ __align__(16) float g_dwf[CC*9];
__device__ __align__(16) float g_dbf[CC];
__device__ __align__(16) float g_kv[BB*NHEADS*HD*HD];
__device__ __align__(16) float g_ksum[BB*NHEADS*HD];

// fp16 activation buffers
__device__ __align__(16) h16 g_xh[SZ];
__device__ __align__(16) h16 g_cmid[SZ];         // conv mid (cw1 out, dwconv in)
__device__ __align__(16) h16 g_dwh[SZ];
__device__ __align__(16) h16 g_x1h[SZ];
__device__ __align__(16) h16 g_x2h[SZ];
__device__ __align__(16) h16 g_qkvh16[3*SZ];     // phi(q),phi(k),v
__device__ __align__(16) h16 g_aoh[SZ];
__device__ __align__(16) h16 g_lnh[SZ];
__device__ __align__(16) h16 g_hmh[4*SZ];
// fp16 weights
__device__ __align__(16) h16 g_w1fh[CC*CC];
__device__ __align__(16) h16 g_cw2h[CC*CC];
__device__ __align__(16) h16 g_qkvh[3*CC*CC];
__device__ __align__(16) h16 g_projh[CC*CC];
__device__ __align__(16) h16 g_w1th[CC*4*CC];
__device__ __align__(16) h16 g_w2th[CC*4*CC];

// ---------------- helpers ----------------
__device__ __forceinline__ void ldsm4(uint32_t* r, uint32_t a) {
    asm volatile("ldmatrix.sync.aligned.m8n8.x4.shared.b16 {%0,%1,%2,%3}, [%4];"
                 : "=r"(r[0]), "=r"(r[1]), "=r"(r[2]), "=r"(r[3]) : "r"(a));
}
__device__ __forceinline__ void ldsm4t(uint32_t* r, uint32_t a) {
    asm volatile("ldmatrix.sync.aligned.m8n8.x4.trans.shared.b16 {%0,%1,%2,%3}, [%4];"
                 : "=r"(r[0]), "=r"(r[1]), "=r"(r[2]), "=r"(r[3]) : "r"(a));
}
__device__ __forceinline__ void mma16816(float* c, const uint32_t* a, const uint32_t* b) {
    asm volatile("mma.sync.aligned.m16n8k16.row.col.f32.f16.f16.f32 "
                 "{%0,%1,%2,%3}, {%4,%5,%6,%7}, {%8,%9}, {%0,%1,%2,%3};"
                 : "+f"(c[0]), "+f"(c[1]), "+f"(c[2]), "+f"(c[3])
                 : "r"(a[0]), "r"(a[1]), "r"(a[2]), "r"(a[3]), "r"(b[0]), "r"(b[1]));
}
__device__ __forceinline__ void cpa16(uint32_t dst, const void* src) {
    asm volatile("cp.async.cg.shared.global [%0], [%1], 16;" :: "r"(dst), "l"(src));
}

// ---------------- BN1 folding (per-row reduction) ----------------
__global__ void fold_bn1_kernel(const float* __restrict__ cw1, const float* __restrict__ cb1,
                                const float* __restrict__ w, const float* __restrict__ bvec,
                                const float* __restrict__ m, const float* __restrict__ v) {
    int o = blockIdx.x;
    int tid = threadIdx.x;   // 128
    float part = 0.f;
    for (int i = tid; i < CC; i += 128) {
        float s = w[i] * rsqrtf(v[i] + 1e-5f);
        float t = bvec[i] - m[i] * s;
        float cv = cw1[o*CC + i];
        g_w1fh[o*CC + i] = __float2half_rn(cv * s);
        part += cv * t;
    }
    __shared__ float red[128];
    red[tid] = part; __syncthreads();
    for (int st = 64; st > 0; st >>= 1) { if (tid < st) red[tid] += red[tid+st]; __syncthreads(); }
    if (tid == 0) g_b1f[o] = cb1[o] + red[0];
}

// ---------------- fused elementwise prep ----------------
#define P0 384
#define P1 (P0 + BB*NHEADS*HD*HD + BB*NHEADS*HD)
#define P2 (P1 + CC*CC)
#define P3 (P2 + 3*CC*CC)
#define P4 (P3 + CC*CC)
#define P5 (P4 + CC*4*CC)
#define P6 (P5 + CC*4*CC)

__global__ void prep_all_kernel(const float* __restrict__ dw, const float* __restrict__ db,
                                const float* __restrict__ bw, const float* __restrict__ bb,
                                const float* __restrict__ bm, const float* __restrict__ bv,
                                const float* __restrict__ cw2, const float* __restrict__ qkv_w,
                                const float* __restrict__ proj_w,
                                const float* __restrict__ mlp_w1, const float* __restrict__ mlp_w2) {
    int i = blockIdx.x * 256 + threadIdx.x;
    if (i < P0) {
        int c = i;
        float s = bw[c] * rsqrtf(bv[c] + 1e-5f);
        float t = bb[c] - bm[c] * s;
        #pragma unroll
        for (int k = 0; k < 9; k++) g_dwf[c*9 + k] = dw[c*9 + k] * s;
        g_dbf[c] = db[c] * s + t;
    } else if (i < P1) {
        int j = i - P0;
        if (j < BB*NHEADS*HD*HD) g_kv[j] = 0.f;
        else g_ksum[j - BB*NHEADS*HD*HD] = 0.f;
    } else if (i < P2) {
        int j = i - P1; g_cw2h[j] = __float2half_rn(cw2[j]);
    } else if (i < P3) {
        int j = i - P2; g_qkvh[j] = __float2half_rn(qkv_w[j]);
    } else if (i < P4) {
        int j = i - P3; g_projh[j] = __float2half_rn(proj_w[j]);
    } else if (i < P5) {
        int j = i - P4;            // w1t: (1536 x 384) from (384 x 1536)
        int a = j / CC, bcol = j - a * CC;
        g_w1th[j] = __float2half_rn(mlp_w1[bcol * (4*CC) + a]);
    } else if (i < P6) {
        int j = i - P5;            // w2t: (384 x 1536) from (1536 x 384)
        int a = j / (4*CC), bcol = j - a * (4*CC);
        g_w2th[j] = __float2half_rn(mlp_w2[bcol * CC + a]);
    }
}

__global__ void tohalf_kernel(const float* __restrict__ src, h16* __restrict__ h, int n) {
    int i = blockIdx.x * 256 + threadIdx.x;
    if (i < n) h[i] = __float2half_rn(src[i]);
}

// ---------------- fp16 GEMM (tensor core, 3-stage cp.async pipeline) ----------------
// Y[b,o,n] = act(W[o,:]·X[b,:,n] + bias[o]) (+ res32 / + res16), fp16 in, fp32 accum.
// ACT: 0=none, 1=gelu, 2=phi on rows<2*CC.
// BM=128, BN=64, BK=32, 128 threads, 4 warps (2m x 2n), warp tile 64x32.
#define SM_B    8192
#define STAGE   12288

template<int ACT>
__global__ __launch_bounds__(128)
void gemm_f16(const h16* __restrict__ Wh, const h16* __restrict__ Xh,
              const float* __restrict__ bias,
              const float* __restrict__ res, const h16* __restrict__ resH,
              float* __restrict__ YF, h16* __restrict__ YH,
              int Cout, int K) {
    const int b  = blockIdx.z;
    const int m0 = blockIdx.y * 128;
    const int n0 = blockIdx.x * 64;
    const h16* Xhb = Xh + (size_t)b * K * GN;
    const size_t obase = (size_t)b * Cout * GN;

    __shared__ __align__(16) unsigned char smraw[3 * STAGE];
    const uint32_t smbase = (uint32_t)__cvta_generic_to_shared(smraw);

    const int tid  = threadIdx.x;
    const int lane = tid & 31;
    const int wid  = tid >> 5;
    const int warp_m = wid & 1;
    const int warp_n = wid >> 1;
    const int m_base = warp_m * 64;
    const int n_base = warp_n * 32;

    const int r8   = (lane & 7) + ((lane >> 3) & 1) * 8;
    const int cadd = lane >> 4;

    float acc[4][4][4];
    #pragma unroll
    for (int i = 0; i < 4; i++)
        #pragma unroll
        for (int nt = 0; nt < 4; nt++)
            #pragma unroll
            for (int q = 0; q < 4; q++) acc[i][nt][q] = 0.f;

    const int ca  = tid & 3;
    const int cam = tid >> 2;
    const int cb  = tid & 7;
    const int cbm = tid >> 3;

    auto issue_tile = [&](int k0, int s) {
        uint32_t sb = smbase + s * STAGE;
        #pragma unroll
        for (int h = 0; h < 4; h++) {
            int m = cam + 32*h;
            uint32_t d = sb + m*64 + ((ca ^ ((m >> 1) & 3)) << 4);
            cpa16(d, Wh + (size_t)(m0 + m) * K + k0 + ca*8);
        }
        #pragma unroll
        for (int h = 0; h < 2; h++) {
            int k = cbm + 16*h;
            uint32_t d = sb + SM_B + k*128 + ((cb ^ (k & 7)) << 4);
            cpa16(d, Xhb + (size_t)(k0 + k) * GN + n0 + cb*8);
        }
        asm volatile("cp.async.commit_group;" ::: "memory");
    };

    const int NT = K >> 5;
    issue_tile(0, 0);
    issue_tile(32, 1);
    int sidx = 0;
    for (int t = 0; t < NT; t++) {
        if (t + 2 < NT) {
            asm volatile("cp.async.wait_group 1;" ::: "memory");
        } else {
            asm volatile("cp.async.wait_group 0;" ::: "memory");
        }
        __syncthreads();
        if (t + 2 < NT) {
            int s2 = sidx + 2; if (s2 >= 3) s2 -= 3;
            issue_tile((t + 2) * 32, s2);
        }
        uint32_t sb = smbase + sidx * STAGE;

        #pragma unroll
        for (int j = 0; j < 2; j++) {
            uint32_t ah[4][4], bh[4][2];
            #pragma unroll
            for (int i = 0; i < 4; i++) {
                int row = m_base + 16*i + r8;
                int ch = 2*j + cadd;
                ldsm4(ah[i], sb + row*64 + ((ch ^ ((row >> 1) & 3)) << 4));
            }
            #pragma unroll
            for (int u = 0; u < 2; u++) {
                int rowk = 16*j + r8;
                int nc = warp_n*4 + 2*u + cadd;
                uint32_t t4[4];
                ldsm4t(t4, sb + SM_B + rowk*128 + ((nc ^ (rowk & 7)) << 4));
                bh[2*u][0] = t4[0]; bh[2*u][1] = t4[1];
                bh[2*u+1][0] = t4[2]; bh[2*u+1][1] = t4[3];
            }
            #pragma unroll
            for (int i = 0; i < 4; i++)
                #pragma unroll
                for (int nt = 0; nt < 4; nt++)
                    mma16816(acc[i][nt], ah[i], bh[nt]);
        }
        if (++sidx == 3) sidx = 0;
    }

    // epilogue
    const int g = lane >> 2, tc = lane & 3;
    #pragma unroll
    for (int i = 0; i < 4; i++) {
        #pragma unroll
        for (int half = 0; half < 2; half++) {
            int row = m0 + m_base + 16*i + g + 8*half;
            float bv = bias ? bias[row] : 0.f;
            size_t rowoff = obase + (size_t)row * GN;
            bool do_phi = (ACT == 2) && (row < 2*CC);
            #pragma unroll
            for (int nt = 0; nt < 4; nt++) {
                int n = n0 + n_base + 8*nt + tc*2;
                float v0 = acc[i][nt][2*half + 0] + bv;
                float v1 = acc[i][nt][2*half + 1] + bv;
                if (ACT == 1) {
                    v0 = 0.5f * v0 * (1.f + erff(v0 * 0.70710678118654752f));
                    v1 = 0.5f * v1 * (1.f + erff(v1 * 0.70710678118654752f));
                }
                if (ACT == 2 && do_phi) {
                    v0 = expf(0.5f * (2.f*v0 - v0*v0));
                    v1 = expf(0.5f * (2.f*v1 - v1*v1));
                }
                if (res) {
                    float2 r = *reinterpret_cast<const float2*>(res + rowoff + n);
                    v0 += r.x; v1 += r.y;
                }
                if (resH) {
                    __half2 rh = *reinterpret_cast<const __half2*>(resH + rowoff + n);
                    v0 += __half2float(rh.x); v1 += __half2float(rh.y);
                }
                if (YF) *reinterpret_cast<float2*>(YF + rowoff + n) = make_float2(v0, v1);
                if (YH) {
                    __half2 ph; ph.x = __float2half_rn(v0); ph.y = __float2half_rn(v1);
                    *reinterpret_cast<__half2*>(YH + rowoff + n) = ph;
                }
            }
        }
    }
}

template<int ACT>
static void run_gemm(const h16* Wh, const h16* Xh, const float* bias,
                     const float* res, const h16* resH,
                     float* YF, h16* YH, int Cout, int K) {
    dim3 g(GN/64, Cout/128, BB), blk(128);
    gemm_f16<ACT><<<g, blk>>>(Wh, Xh, bias, res, resH, YF, YH, Cout, K);
}

// ---------------- depthwise 3x3 (BN2-folded), fp16 in/out ----------------
__global__ __launch_bounds__(256)
void dwconv_kernel(const h16* __restrict__ in, h16* __restrict__ oh) {
    int bc = blockIdx.x;          // b*CC + c
    int c  = bc % CC;
    __shared__ float tile[58*58];
    const h16* plane = in + (size_t)bc * GN;
    int tid = threadIdx.x;
    for (int idx = tid; idx < 58*58; idx += 256) {
        int ty = idx / 58, tx = idx - ty*58;
        int y = ty - 1, xq = tx - 1;
        float v = 0.f;
        if (y >= 0 && y < 56 && xq >= 0 && xq < 56) v = __half2float(plane[y*56 + xq]);
        tile[idx] = v;
    }
    __syncthreads();
    float w0=g_dwf[c*9+0], w1=g_dwf[c*9+1], w2=g_dwf[c*9+2];
    float w3=g_dwf[c*9+3], w4=g_dwf[c*9+4], w5=g_dwf[c*9+5];
    float w6=g_dwf[c*9+6], w7=g_dwf[c*9+7], w8=g_dwf[c*9+8];
    float bbv = g_dbf[c];
    h16* ohp = oh + (size_t)bc * GN;
    for (int p = tid; p < GN; p += 256) {
        int y = p / 56, xq = p - y*56;
        const float* t = &tile[y*58 + xq];
        float a = bbv + w0*t[0] + w1*t[1] + w2*t[2]
                      + w3*t[58] + w4*t[59] + w5*t[60]
                      + w6*t[116] + w7*t[117] + w8*t[118];
        ohp[p] = __float2half_rn(a);
    }
}

// ---------------- linear attention (qkv already phi-transformed for q,k) ----------------
// j-tile = 98: two sub-tiles per 196-position block.
__global__ __launch_bounds__(256)
void attn_kv_kernel(const h16* __restrict__ qkv) {
    int bh = blockIdx.x; int b = bh >> 3, hd = bh & 7;
    int n0 = blockIdx.y * 196;
    __shared__ float kp_s[98*48];
    __shared__ float vv_s[98*48];
    int tid = threadIdx.x;
    int dr[9], er[9];
    #pragma unroll
    for (int r = 0; r < 9; r++) { int de = tid + 256*r; dr[r] = de/48; er[r] = de - dr[r]*48; }
    float acc[9];
    #pragma unroll
    for (int r = 0; r < 9; r++) acc[r] = 0.f;
    float ks = 0.f;
    const h16* kbase = qkv + ((size_t)(b*1152 + CC   + hd*HD)) * GN + n0;
    const h16* vbase = qkv + ((size_t)(b*1152 + 2*CC + hd*HD)) * GN + n0;
    for (int j0 = 0; j0 < 196; j0 += 98) {
        for (int idx = tid; idx < 48*98; idx += 256) {
            int d = idx / 98, j = idx - d*98;
            kp_s[j*48 + d] = __half2float(kbase[(size_t)d*GN + j0 + j]);
            vv_s[j*48 + d] = __half2float(vbase[(size_t)d*GN + j0 + j]);
        }
        __syncthreads();
        #pragma unroll 2
        for (int j = 0; j < 98; j++) {
            #pragma unroll
            for (int r = 0; r < 9; r++)
                acc[r] = fmaf(kp_s[j*48 + dr[r]], vv_s[j*48 + er[r]], acc[r]);
        }
        if (tid < 48) {
            float s = 0.f;
            #pragma unroll 2
            for (int j = 0; j < 98; j++) s += kp_s[j*48 + tid];
            ks += s;
        }
        __syncthreads();
    }
    #pragma unroll
    for (int r = 0; r < 9; r++) atomicAdd(&g_kv[bh*2304 + tid + 256*r], acc[r]);
    if (tid < 48) atomicAdd(&g_ksum[bh*48 + tid], ks);
}

__global__ __launch_bounds__(256)
void attn_out_kernel(const h16* __restrict__ qkv, h16* __restrict__ oh) {
    int bh = blockIdx.x; int b = bh >> 3, hd = bh & 7;
    int n0 = blockIdx.y * 196;
    __shared__ float kv_s[2304];
    __shared__ float ks_s[48];
    __shared__ float qp_s[98*49];
    __shared__ float dinv[98];
    int tid = threadIdx.x;
    for (int i = tid; i < 2304; i += 256) kv_s[i] = g_kv[bh*2304 + i];
    if (tid < 48) ks_s[tid] = g_ksum[bh*48 + tid];
    __syncthreads();
    const h16* qbase = qkv + ((size_t)(b*1152 + hd*HD)) * GN + n0;
    size_t ob = ((size_t)(b*CC + hd*HD)) * GN + n0;
    for (int j0 = 0; j0 < 196; j0 += 98) {
        for (int idx = tid; idx < 48*98; idx += 256) {
            int d = idx / 98, j = idx - d*98;
            qp_s[j*49 + d] = __half2float(qbase[(size_t)d*GN + j0 + j]);
        }
        __syncthreads();
        if (tid < 98) {
            float s = 0.f;
            #pragma unroll
            for (int d = 0; d < 48; d++) s = fmaf(qp_s[tid*49 + d], ks_s[d], s);
            dinv[tid] = 1.f / (s + 1e-6f);
        }
        __syncthreads();
        for (int idx = tid; idx < 48*98; idx += 256) {
            int e = idx / 98, j = idx - e*98;
            float s = 0.f;
            #pragma unroll
            for (int d = 0; d < 48; d++) s = fmaf(qp_s[j*49 + d], kv_s[d*48 + e], s);
            oh[ob + (size_t)e*GN + j0 + j] = __float2half_rn(s * dinv[j]);
        }
        __syncthreads();
    }
}

// ---------------- LayerNorm over channels, fp16 in, writes fp16 ----------------
__global__ __launch_bounds__(256)
void ln_kernel(const h16* __restrict__ x2, const float* __restrict__ lw,
               const float* __restrict__ lb, h16* __restrict__ oh) {
    int b = blockIdx.y; int n0 = blockIdx.x * 16;
    __shared__ float s[CC*17];
    __shared__ float r1[256], r2[256];
    __shared__ float mu[16], ri[16];
    const h16* base = x2 + (size_t)b * CC * GN + n0;
    int tid = threadIdx.x;
    for (int idx = tid; idx < CC*16; idx += 256) {
        int c = idx >> 4, j = idx & 15;
        s[c*17 + j] = __half2float(base[(size_t)c * GN + j]);
    }
    __syncthreads();
    {
        int j = tid & 15, part = tid >> 4;
        float sm = 0.f, sq = 0.f;
        for (int c = part*24; c < part*24 + 24; c++) {
            float v = s[c*17 + j]; sm += v; sq = fmaf(v, v, sq);
        }
        r1[tid] = sm; r2[tid] = sq;
    }
    __syncthreads();
    if (tid < 16) {
        float a = 0.f, q = 0.f;
        #pragma unroll
        for (int p = 0; p < 16; p++) { a += r1[p*16 + tid]; q += r2[p*16 + tid]; }
        float mean = a * (1.f/384.f);
        float var = q * (1.f/384.f) - mean*mean;
        mu[tid] = mean; ri[tid] = rsqrtf(var + 1e-5f);
    }
    __syncthreads();
    size_t ob = (size_t)b * CC * GN + n0;
    for (int idx = tid; idx < CC*16; idx += 256) {
        int c = idx >> 4, j = idx & 15;
        float v = (s[c*17 + j] - mu[j]) * ri[j] * lw[c] + lb[c];
        oh[ob + (size_t)c * GN + j] = __float2half_rn(v);
    }
}

// ---------------- launch ----------------
extern "C" void kernel_launch(void* const* d_in, const int* in_sizes, int n_in,
                              void* d_out, int out_size) {
    const float* x      = (const float*)d_in[0];
    const float* bn1_w  = (const float*)d_in[1];
    const float* bn1_b  = (const float*)d_in[2];
    const float* bn1_m  = (const float*)d_in[3];
    const float* bn1_v  = (const float*)d_in[4];
    const float* cw1    = (const float*)d_in[5];
    const float* cb1    = (const float*)d_in[6];
    const float* dw     = (const float*)d_in[7];
    const float* db     = (const float*)d_in[8];
    const float* bn2_w  = (const float*)d_in[9];
    const float* bn2_b  = (const float*)d_in[10];
    const float* bn2_m  = (const float*)d_in[11];
    const float* bn2_v  = (const float*)d_in[12];
    const float* cw2    = (const float*)d_in[13];
    const float* cb2    = (const float*)d_in[14];
    const float* qkv_w  = (const float*)d_in[15];
    const float* proj_w = (const float*)d_in[16];
    const float* proj_b = (const float*)d_in[17];
    const float* ln_w   = (const float*)d_in[18];
    const float* ln_b   = (const float*)d_in[19];
    const float* mlp_w1 = (const float*)d_in[20];
    const float* mlp_b1 = (const float*)d_in[21];
    const float* mlp_w2 = (const float*)d_in[22];
    const float* mlp_b2 = (const float*)d_in[23];

    // symbol addresses
    float *b1f;
    h16 *xh,*cmid,*dwh,*x1h,*x2h,*qkvh16,*aoh,*lnh,*hmh;
    h16 *w1fh,*cw2h,*qkvh,*projh,*w1th,*w2th;
    cudaGetSymbolAddress((void**)&b1f,  g_b1f);
    cudaGetSymbolAddress((void**)&xh,  g_xh);
    cudaGetSymbolAddress((void**)&cmid, g_cmid);
    cudaGetSymbolAddress((void**)&dwh, g_dwh);
    cudaGetSymbolAddress((void**)&x1h, g_x1h);
    cudaGetSymbolAddress((void**)&x2h, g_x2h);
    cudaGetSymbolAddress((void**)&qkvh16, g_qkvh16);
    cudaGetSymbolAddress((void**)&aoh, g_aoh);
    cudaGetSymbolAddress((void**)&lnh, g_lnh);
    cudaGetSymbolAddress((void**)&hmh, g_hmh);
    cudaGetSymbolAddress((void**)&w1fh, g_w1fh);
    cudaGetSymbolAddress((void**)&cw2h, g_cw2h);
    cudaGetSymbolAddress((void**)&qkvh, g_qkvh);
    cudaGetSymbolAddress((void**)&projh, g_projh);
    cudaGetSymbolAddress((void**)&w1th, g_w1th);
    cudaGetSymbolAddress((void**)&w2th, g_w2th);

    // weight prep (3 launches)
    fold_bn1_kernel<<<CC, 128>>>(cw1, cb1, bn1_w, bn1_b, bn1_m, bn1_v);
    prep_all_kernel<<<(P6 + 255)/256, 256>>>(dw, db, bn2_w, bn2_b, bn2_m, bn2_v,
                                             cw2, qkv_w, proj_w, mlp_w1, mlp_w2);
    tohalf_kernel<<<(SZ + 255)/256, 256>>>(x, xh, SZ);

    // conv path
    run_gemm<0>(w1fh, xh, b1f, nullptr, nullptr, nullptr, cmid, CC, CC);
    dwconv_kernel<<<BB*CC, 256>>>(cmid, dwh);
    run_gemm<0>(cw2h, dwh, cb2, nullptr, xh, nullptr, x1h, CC, CC);   // x1 = 1x1 + x(h) -> fp16

    // linear attention (phi fused into qkv epilogue)
    run_gemm<2>(qkvh, x1h, nullptr, nullptr, nullptr, nullptr, qkvh16, 3*CC, CC);
    attn_kv_kernel<<<dim3(BB*NHEADS, 16), 256>>>(qkvh16);
    attn_out_kernel<<<dim3(BB*NHEADS, 16), 256>>>(qkvh16, aoh);
    run_gemm<0>(projh, aoh, proj_b, nullptr, x1h, nullptr, x2h, CC, CC);  // x2 = proj + x1 -> fp16

    // LN + MLP
    ln_kernel<<<dim3(GN/16, BB), 256>>>(x2h, ln_w, ln_b, lnh);
    run_gemm<1>(w1th, lnh, mlp_b1, nullptr, nullptr, nullptr, hmh, 4*CC, CC);        // gelu(fc1)
    run_gemm<0>(w2th, hmh, mlp_b2, nullptr, x2h, (float*)d_out, nullptr, CC, 4*CC);  // out = x2 + fc2
}